// round 11
// baseline (speedup 1.0000x reference)
#include <cuda_runtime.h>
#include <math.h>

#define H    512
#define NH   8
#define DH   64
#define NLAY 2
#define NPRED 26
#define MAXF 5
#define FFD  2048
#define BSZ  16
#define TC   10
#define NOBJ 20
#define NP   380   /* NOBJ*(NOBJ-1) */

#define NBLK   148
#define NTHR   512
#define NWARPS (NBLK * 16)

// ---------------- scratch (device globals; no allocation) ----------------
__device__ __align__(16) float g_px  [BSZ*MAXF*H];
__device__ __align__(16) float g_qkv [BSZ*MAXF*3*H];
__device__ __align__(16) float g_kv  [NLAY*BSZ*TC*2*H];
__device__ __align__(16) float g_att [BSZ*MAXF*H];
__device__ __align__(16) float g_proj[BSZ*MAXF*H];
__device__ __align__(16) float g_ffh [BSZ*MAXF*FFD];
__device__ __align__(16) float g_ctx [BSZ*MAXF*H];
__device__ __align__(16) float g_sw  [BSZ*NOBJ*H];
__device__ __align__(16) float g_ow  [BSZ*NOBJ*H];
__device__ __align__(16) float g_cw  [BSZ*MAXF*H];
__device__ __align__(16) float g_wf  [27*H];
__device__ float g_bf [32];

// grid barrier state (zero-init; self-resetting, replay-safe)
__device__ int          g_bcnt;
__device__ volatile int g_epoch;

__device__ __forceinline__ float gelu_f(float x) {
    return 0.5f * x * (1.0f + erff(x * 0.70710678118654752440f));
}

// packed f32x2 FMA (sm_103a FFMA2)
__device__ __forceinline__ void ffma2(unsigned long long& d, unsigned long long a,
                                      unsigned long long b) {
    asm("fma.rn.f32x2 %0, %1, %2, %0;" : "+l"(d) : "l"(a), "l"(b));
}
__device__ __forceinline__ float unpack_sum(unsigned long long v) {
    return __uint_as_float((unsigned)(v & 0xffffffffull)) +
           __uint_as_float((unsigned)(v >> 32));
}
__device__ __forceinline__ float wred(float v) {
    v += __shfl_xor_sync(0xffffffffu, v, 16);
    v += __shfl_xor_sync(0xffffffffu, v, 8);
    v += __shfl_xor_sync(0xffffffffu, v, 4);
    v += __shfl_xor_sync(0xffffffffu, v, 2);
    v += __shfl_xor_sync(0xffffffffu, v, 1);
    return v;
}

// software grid barrier: release (threadfence) -> arrive -> spin -> L1 inval
__device__ __forceinline__ void gbar() {
    __syncthreads();
    if (threadIdx.x == 0) {
        __threadfence();
        int e = g_epoch;
        if (atomicAdd(&g_bcnt, 1) == NBLK - 1) {
            g_bcnt = 0;
            __threadfence();
            g_epoch = e + 1;
        } else {
            while (g_epoch == e) { }
        }
    }
    __syncthreads();
    __threadfence();   // gpu-scope fence -> CCTL.IVALL: fresh L1 for this phase
}

// ---------------- GEMM phase: warp-per-tile (2m x 8n), lane-split K ----------
// C[M,N] = act(A @ W^T + bias); W rows stride ldw. K%128==0, M even, N%8==0.
__device__ void gemm_phase(int gw, const float* __restrict__ A,
                           const float* __restrict__ W, const float* __restrict__ bias,
                           float* __restrict__ C, int M, int N, int K, int ldw,
                           int act, int bcmod)
{
    int lane = threadIdx.x & 31;
    int mh = M >> 1;
    int ntiles = mh * (N >> 3);
    for (int t = gw; t < ntiles; t += NWARPS) {
        int m0 = (t % mh) * 2;
        int n0 = (t / mh) * 8;
        int mm0 = bcmod ? (m0 % bcmod) : m0;
        int mm1 = bcmod ? ((m0 + 1) % bcmod) : (m0 + 1);
        const float* a0 = A + (long)mm0 * K + lane * 4;
        const float* a1 = A + (long)mm1 * K + lane * 4;
        const float* wb = W + (long)n0 * ldw + lane * 4;

        unsigned long long acc[2][8];
        #pragma unroll
        for (int j = 0; j < 8; j++) { acc[0][j] = 0ull; acc[1][j] = 0ull; }

        for (int k = 0; k < K; k += 128) {
            ulonglong2 av0 = *(const ulonglong2*)(a0 + k);
            ulonglong2 av1 = *(const ulonglong2*)(a1 + k);
            #pragma unroll
            for (int j = 0; j < 8; j++) {
                ulonglong2 bv = *(const ulonglong2*)(wb + (long)j * ldw + k);
                ffma2(acc[0][j], av0.x, bv.x); ffma2(acc[0][j], av0.y, bv.y);
                ffma2(acc[1][j], av1.x, bv.x); ffma2(acc[1][j], av1.y, bv.y);
            }
        }
        #pragma unroll
        for (int i = 0; i < 2; i++)
            #pragma unroll
            for (int j = 0; j < 8; j++) {
                float v = wred(unpack_sum(acc[i][j]));
                if (lane == 0) {
                    int n = n0 + j;
                    float r = v + (bias ? bias[n] : 0.f);
                    if (act) r = gelu_f(r);
                    C[(long)(m0 + i) * N + n] = r;
                }
            }
    }
}

// ---------------- attention phase: warp per (batch, head) --------------------
__device__ void attn_phase(int gw, const float* __restrict__ q, int qstride,
                           const float* __restrict__ kv, int kvstride, int koff, int voff,
                           int Tq, int Tk, float* __restrict__ att, float* sbuf)
{
    int lane = threadIdx.x & 31;
    int wid = threadIdx.x >> 5;
    float* sc = sbuf + wid * 64;   // per-warp scratch (Tq*Tk <= 50)
    for (int u = gw; u < BSZ * NH; u += NWARPS) {
        int b = u / NH, h = u % NH;
        for (int idx = lane; idx < Tq * Tk; idx += 32) {
            int ti = idx / Tk, tj = idx - ti * Tk;
            const float* qp = q + (long)(b * Tq + ti) * qstride + h * DH;
            const float* kp = kv + (long)(b * Tk + tj) * kvstride + koff + h * DH;
            float s = 0.f;
            #pragma unroll
            for (int d = 0; d < DH; d += 4) {
                float4 qv = *(const float4*)(qp + d);
                float4 kvv = *(const float4*)(kp + d);
                s += qv.x * kvv.x + qv.y * kvv.y + qv.z * kvv.z + qv.w * kvv.w;
            }
            sc[idx] = s * 0.125f;
        }
        __syncwarp();
        if (lane < Tq) {
            float* row = sc + lane * Tk;
            float mx = -1e30f;
            for (int j = 0; j < Tk; j++) mx = fmaxf(mx, row[j]);
            float sum = 0.f;
            for (int j = 0; j < Tk; j++) { float e = expf(row[j] - mx); row[j] = e; sum += e; }
            float inv = 1.f / sum;
            for (int j = 0; j < Tk; j++) row[j] *= inv;
        }
        __syncwarp();
        for (int ti = 0; ti < Tq; ti++) {
            for (int d = lane; d < DH; d += 32) {
                float o = 0.f;
                for (int j = 0; j < Tk; j++)
                    o += sc[ti * Tk + j] * kv[(long)(b * Tk + j) * kvstride + voff + h * DH + d];
                att[(long)(b * Tq + ti) * H + h * DH + d] = o;
            }
        }
        __syncwarp();
    }
}

// ---------------- layernorm phase: warp per row ------------------------------
__device__ void ln_phase(int gw, const float* __restrict__ x, const float* __restrict__ res,
                         int resmod, const float* __restrict__ w, const float* __restrict__ b,
                         float* __restrict__ out, const float* __restrict__ fw,
                         const float* __restrict__ fb, float* __restrict__ ctxout, int Mq)
{
    int lane = threadIdx.x & 31;
    for (int row = gw; row < Mq; row += NWARPS) {
        long rr = resmod ? (row % resmod) : row;
        float4 vv[4];
        float s1 = 0.f, s2 = 0.f;
        #pragma unroll
        for (int q = 0; q < 4; q++) {
            int c = lane * 4 + q * 128;
            float4 a = *(const float4*)&x[(long)row * H + c];
            float4 r = *(const float4*)&res[rr * H + c];
            float4 v = make_float4(a.x + r.x, a.y + r.y, a.z + r.z, a.w + r.w);
            vv[q] = v;
            s1 += v.x + v.y + v.z + v.w;
            s2 += v.x * v.x + v.y * v.y + v.z * v.z + v.w * v.w;
        }
        s1 = wred(s1); s2 = wred(s2);
        float mean = s1 * (1.f / H);
        float var = s2 * (1.f / H) - mean * mean;
        float inv = rsqrtf(var + 1e-5f);
        float4 yv[4];
        float t1 = 0.f, t2 = 0.f;
        #pragma unroll
        for (int q = 0; q < 4; q++) {
            int c = lane * 4 + q * 128;
            float4 wv = *(const float4*)&w[c];
            float4 bv = *(const float4*)&b[c];
            float4 y;
            y.x = (vv[q].x - mean) * inv * wv.x + bv.x;
            y.y = (vv[q].y - mean) * inv * wv.y + bv.y;
            y.z = (vv[q].z - mean) * inv * wv.z + bv.z;
            y.w = (vv[q].w - mean) * inv * wv.w + bv.w;
            yv[q] = y;
            *(float4*)&out[(long)row * H + c] = y;
            t1 += y.x + y.y + y.z + y.w;
            t2 += y.x * y.x + y.y * y.y + y.z * y.z + y.w * y.w;
        }
        if (fw) {
            t1 = wred(t1); t2 = wred(t2);
            float m2 = t1 * (1.f / H);
            float v2 = t2 * (1.f / H) - m2 * m2;
            float i2 = rsqrtf(v2 + 1e-5f);
            #pragma unroll
            for (int q = 0; q < 4; q++) {
                int c = lane * 4 + q * 128;
                float4 fwv = *(const float4*)&fw[c];
                float4 fbv = *(const float4*)&fb[c];
                float4 z;
                z.x = (yv[q].x - m2) * i2 * fwv.x + fbv.x;
                z.y = (yv[q].y - m2) * i2 * fwv.y + fbv.y;
                z.z = (yv[q].z - m2) * i2 * fwv.z + fbv.z;
                z.w = (yv[q].w - m2) * i2 * fwv.w + fbv.w;
                *(float4*)&ctxout[(long)row * H + c] = z;
            }
        }
    }
}

// ---------------- fused pe2 head weights: wf = Wc @ pe2, bf -------------------
__device__ void wf_phase(int gw, const float* __restrict__ pred_w, const float* __restrict__ pred_b,
                         const float* __restrict__ ex_w, const float* __restrict__ ex_b,
                         const float* __restrict__ pe2_w, const float* __restrict__ pe2_b)
{
    int lane = threadIdx.x & 31;
    // tasks 0..107: wf 128-col chunks;  108..134: bf
    for (int t = gw; t < 27 * 4 + 27; t += NWARPS) {
        if (t < 108) {
            int j = t >> 2;
            int c0 = (t & 3) * 128 + lane * 4;
            const float* wc = (j < NPRED) ? (pred_w + j * H) : ex_w;
            float4 s = make_float4(0.f, 0.f, 0.f, 0.f);
            for (int o = 0; o < H; o += 4) {
                #pragma unroll
                for (int oo = 0; oo < 4; oo++) {
                    float w = wc[o + oo];
                    float4 p = *(const float4*)&pe2_w[(long)(o + oo) * H + c0];
                    s.x += w * p.x; s.y += w * p.y; s.z += w * p.z; s.w += w * p.w;
                }
            }
            *(float4*)&g_wf[j * H + c0] = s;
        } else {
            int j = t - 108;
            const float* wc = (j < NPRED) ? (pred_w + j * H) : ex_w;
            float bs = 0.f;
            for (int o = lane; o < H; o += 32) bs += wc[o] * pe2_b[o];
            bs = wred(bs);
            if (lane == 0) g_bf[j] = ((j < NPRED) ? pred_b[j] : ex_b[0]) + bs;
        }
    }
}

// ---------------- pair head phase (block-level, smem staging) ----------------
__device__ void pair_phase(float* __restrict__ out, int Fh, int Rtot, float* sbuf)
{
    int tid = threadIdx.x;
    int wid = tid >> 5, lane = tid & 31;
    int ngroups = (Rtot + 15) >> 4;
    for (int g = blockIdx.x; g < ngroups; g += NBLK) {
        int row0 = g << 4;
        __syncthreads();
        for (int e = tid; e < 16 * H; e += NTHR) {
            int r = e >> 9, c = e & (H - 1);
            int row = row0 + r;
            float hv = 0.f;
            if (row < Rtot) {
                int p = row % NP;
                int bfi = row / NP;
                int f = bfi % Fh;
                int b = bfi / Fh;
                int i = p / (NOBJ - 1);
                int jr = p % (NOBJ - 1);
                int jo = jr + (jr >= i ? 1 : 0);
                hv = g_sw[(long)(b * NOBJ + i) * H + c] + g_ow[(long)(b * NOBJ + jo) * H + c]
                   + g_cw[(long)(b * Fh + f) * H + c];
                hv = gelu_f(hv);
            }
            sbuf[r * H + c] = hv;
        }
        __syncthreads();
        for (int o = wid; o < 16 * 27; o += 16) {
            int r = o & 15, j = o >> 4;
            float acc = 0.f;
            #pragma unroll
            for (int qq = 0; qq < 4; qq++) {
                int c = lane * 4 + qq * 128;
                float4 hv = *(const float4*)&sbuf[r * H + c];
                float4 wv = *(const float4*)&g_wf[j * H + c];
                acc += hv.x * wv.x + hv.y * wv.y + hv.z * wv.z + hv.w * wv.w;
            }
            acc = wred(acc);
            if (lane == 0) {
                int row = row0 + r;
                if (row < Rtot) {
                    acc += g_bf[j];
                    if (j < NPRED) out[(long)row * NPRED + j] = acc;
                    else           out[(long)Rtot * NPRED + row] = acc;
                }
            }
        }
    }
}

// ---------------- the persistent kernel --------------------------------------
__global__ void __launch_bounds__(NTHR, 1) k_all(
    const float* tctx, const float* objf, const float* fq,
    const float* sa_in_w, const float* sa_in_b,
    const float* sa_out_w, const float* sa_out_b,
    const float* ca_in_w, const float* ca_in_b,
    const float* ca_out_w, const float* ca_out_b,
    const float* ff1_w, const float* ff1_b,
    const float* ff2_w, const float* ff2_b,
    const float* n1_w, const float* n1_b,
    const float* n2_w, const float* n2_b,
    const float* n3_w, const float* n3_b,
    const float* norm_w, const float* norm_b,
    const float* pe1_w, const float* pe1_b,
    const float* pe2_w, const float* pe2_b,
    const float* pred_w, const float* pred_b,
    const float* ex_w, const float* ex_b,
    float* out, int Fh)
{
    __shared__ float sbuf[16 * H];   // 32 KB: attn scratch / pair staging
    int gw = blockIdx.x * 16 + (threadIdx.x >> 5);
    int Mq = BSZ * Fh;

    // phase A: all input-only work (head precompute + layer0 SA qkv)
    gemm_phase(gw, objf, pe1_w,     nullptr, g_sw, BSZ * NOBJ, H, H, 3 * H, 0, 0);
    gemm_phase(gw, objf, pe1_w + H, nullptr, g_ow, BSZ * NOBJ, H, H, 3 * H, 0, 0);
    gemm_phase(gw, tctx, ca_in_w + (long)H * H, ca_in_b + H,
               g_kv, BSZ * TC, 2 * H, H, H, 0, 0);
    gemm_phase(gw, tctx, ca_in_w + (long)3 * H * H + (long)H * H, ca_in_b + 3 * H + H,
               g_kv + (long)BSZ * TC * 2 * H, BSZ * TC, 2 * H, H, H, 0, 0);
    wf_phase(gw, pred_w, pred_b, ex_w, ex_b, pe2_w, pe2_b);
    gemm_phase(gw, fq, sa_in_w, sa_in_b, g_qkv, Mq, 3 * H, H, H, 0, Fh);
    gbar();

    for (int l = 0; l < NLAY; l++) {
        if (l > 0) {
            gemm_phase(gw, g_px, sa_in_w + (long)l * 3 * H * H, sa_in_b + l * 3 * H,
                       g_qkv, Mq, 3 * H, H, H, 0, 0);
            gbar();
        }
        // SA attention
        attn_phase(gw, g_qkv, 3 * H, g_qkv, 3 * H, H, 2 * H, Fh, Fh, g_att, sbuf);
        gbar();
        gemm_phase(gw, g_att, sa_out_w + (long)l * H * H, sa_out_b + l * H,
                   g_proj, Mq, H, H, H, 0, 0);
        gbar();
        ln_phase(gw, g_proj, (l == 0) ? fq : g_px, (l == 0) ? Fh : 0,
                 n1_w + l * H, n1_b + l * H, g_px, nullptr, nullptr, nullptr, Mq);
        gbar();
        // CA
        gemm_phase(gw, g_px, ca_in_w + (long)l * 3 * H * H, ca_in_b + l * 3 * H,
                   g_qkv, Mq, H, H, H, 0, 0);
        gbar();
        const float* kvl = g_kv + (long)l * BSZ * TC * 2 * H;
        attn_phase(gw, g_qkv, H, kvl, 2 * H, 0, H, Fh, TC, g_att, sbuf);
        gbar();
        gemm_phase(gw, g_att, ca_out_w + (long)l * H * H, ca_out_b + l * H,
                   g_proj, Mq, H, H, H, 0, 0);
        gbar();
        ln_phase(gw, g_proj, g_px, 0, n2_w + l * H, n2_b + l * H, g_px,
                 nullptr, nullptr, nullptr, Mq);
        gbar();
        // FFN
        gemm_phase(gw, g_px, ff1_w + (long)l * FFD * H, ff1_b + l * FFD,
                   g_ffh, Mq, FFD, H, H, 1, 0);
        gbar();
        gemm_phase(gw, g_ffh, ff2_w + (long)l * H * FFD, ff2_b + l * H,
                   g_proj, Mq, H, FFD, FFD, 0, 0);
        gbar();
        int last = (l == NLAY - 1);
        ln_phase(gw, g_proj, g_px, 0, n3_w + l * H, n3_b + l * H, g_px,
                 last ? norm_w : nullptr, last ? norm_b : nullptr, g_ctx, Mq);
        gbar();
    }

    // ctx projection through pe1 ctx slice
    gemm_phase(gw, g_ctx, pe1_w + 2 * H, pe1_b, g_cw, Mq, H, H, 3 * H, 0, 0);
    gbar();

    // pair head
    int Rtot = BSZ * Fh * NP;
    pair_phase(out, Fh, Rtot, sbuf);
}

// ---------------- host orchestration ----------------
extern "C" void kernel_launch(void* const* d_in, const int* in_sizes, int n_in,
                              void* d_out, int out_size)
{
    (void)in_sizes; (void)n_in;
    int Fh = out_size / (BSZ * NP * (NPRED + 1));
    if (Fh < 1) Fh = 1;
    if (Fh > MAXF) Fh = MAXF;

    k_all<<<NBLK, NTHR>>>(
        (const float*)d_in[0],  (const float*)d_in[1],  (const float*)d_in[2],
        (const float*)d_in[3],  (const float*)d_in[4],
        (const float*)d_in[5],  (const float*)d_in[6],
        (const float*)d_in[7],  (const float*)d_in[8],
        (const float*)d_in[9],  (const float*)d_in[10],
        (const float*)d_in[11], (const float*)d_in[12],
        (const float*)d_in[13], (const float*)d_in[14],
        (const float*)d_in[15], (const float*)d_in[16],
        (const float*)d_in[17], (const float*)d_in[18],
        (const float*)d_in[19], (const float*)d_in[20],
        (const float*)d_in[21], (const float*)d_in[22],
        (const float*)d_in[23], (const float*)d_in[24],
        (const float*)d_in[25], (const float*)d_in[26],
        (const float*)d_in[27], (const float*)d_in[28],
        (const float*)d_in[29], (const float*)d_in[30],
        (float*)d_out, Fh);
}

// round 13
// speedup vs baseline: 1.6377x; 1.6377x over previous
#include <cuda_runtime.h>
#include <math.h>

#define H    512
#define NH   8
#define DH   64
#define NLAY 2
#define NPRED 26
#define MAXF 5
#define FFD  2048
#define BSZ  16
#define TC   10
#define NOBJ 20
#define NP   380   /* NOBJ*(NOBJ-1) */

// ---------------- scratch (device globals; no allocation) ----------------
__device__ __align__(16) float g_px  [BSZ*MAXF*H];
__device__ __align__(16) float g_qkv [BSZ*MAXF*3*H];
__device__ __align__(16) float g_kv  [NLAY*BSZ*TC*2*H];
__device__ __align__(16) float g_att [BSZ*MAXF*H];
__device__ __align__(16) float g_proj[4*BSZ*MAXF*H];   // up to 4 K-split slices
__device__ __align__(16) float g_ffh [BSZ*MAXF*FFD];
__device__ __align__(16) float g_ctx [BSZ*MAXF*H];
__device__ __align__(16) float g_sw  [BSZ*NOBJ*H];
__device__ __align__(16) float g_ow  [BSZ*NOBJ*H];
__device__ __align__(16) float g_cw  [BSZ*MAXF*H];
__device__ __align__(16) float g_wf  [32*H];           // rows 27..31 zero
__device__ float g_bf [32];

__device__ __forceinline__ float gelu_f(float x) {
    return 0.5f * x * (1.0f + erff(x * 0.70710678118654752440f));
}

// ---------------- 3xTF32 mma primitives --------------------------------------
__device__ __forceinline__ unsigned tf32_of(float v) {
    unsigned r;
    asm("cvt.rna.tf32.f32 %0, %1;" : "=r"(r) : "f"(v));
    return r;
}
__device__ __forceinline__ void split32(float v, unsigned& h, unsigned& l) {
    h = tf32_of(v);
    float lf = v - __uint_as_float(h);
    l = tf32_of(lf);
}
__device__ __forceinline__ void mma_tf32(float* d, unsigned a0, unsigned a1,
                                         unsigned a2, unsigned a3,
                                         unsigned b0, unsigned b1) {
    asm("mma.sync.aligned.m16n8k8.row.col.f32.tf32.tf32.f32 "
        "{%0,%1,%2,%3},{%4,%5,%6,%7},{%8,%9},{%0,%1,%2,%3};"
        : "+f"(d[0]), "+f"(d[1]), "+f"(d[2]), "+f"(d[3])
        : "r"(a0), "r"(a1), "r"(a2), "r"(a3), "r"(b0), "r"(b1));
}
__device__ __forceinline__ void mma3x(float* d, const unsigned* ah, const unsigned* al,
                                      unsigned bh0, unsigned bh1,
                                      unsigned bl0, unsigned bl1) {
    mma_tf32(d, al[0], al[1], al[2], al[3], bh0, bh1);
    mma_tf32(d, ah[0], ah[1], ah[2], ah[3], bl0, bl1);
    mma_tf32(d, ah[0], ah[1], ah[2], ah[3], bh0, bh1);
}

// ---------------- tensor GEMM tile body (128 thr = 4 warps, 16m x 16n) -------
// C[M,N] = act(A[M,lda restricted] @ W[N,ldw]^T + bias) over K range [k0,k0+klen).
// 4 warps split klen 4-ways; fixed-order smem reduce (deterministic).
// Fragment layout (PTX m16n8k8 tf32): g=lane>>2, t=lane&3;
//   A: a0=(g,t) a1=(g+8,t) a2=(g,t+4) a3=(g+8,t+4)   [rows m0+..., cols k]
//   B: b0=(k=t, n=g) b1=(k=t+4, n=g)                  [B[k][n] = W[n][k]]
//   D: d0=(g,2t) d1=(g,2t+1) d2=(g+8,2t) d3=(g+8,2t+1)
__device__ void tgemm_body(const float* __restrict__ A, int lda,
                           const float* __restrict__ W, int ldw,
                           const float* __restrict__ bias,
                           float* __restrict__ C, int M, int N, int act, int bcmod,
                           int m0, int n0, int k0, int klen, float* red)
{
    int tid = threadIdx.x, warp = tid >> 5, lane = tid & 31;
    int g = lane >> 2, t = lane & 3;
    int Kw = klen >> 2;
    int kb = k0 + warp * Kw;
    int r0 = m0 + g, r1 = m0 + g + 8;
    int mm0 = bcmod ? (r0 % bcmod) : (r0 < M ? r0 : M - 1);
    int mm1 = bcmod ? (r1 % bcmod) : (r1 < M ? r1 : M - 1);
    const float* a0p = A + (long)mm0 * lda;
    const float* a1p = A + (long)mm1 * lda;
    const float* b0p = W + (long)(n0 + g) * ldw;
    const float* b1p = W + (long)(n0 + 8 + g) * ldw;

    float d0[4] = {0.f, 0.f, 0.f, 0.f};
    float d1[4] = {0.f, 0.f, 0.f, 0.f};

    #pragma unroll 4
    for (int kk = kb; kk < kb + Kw; kk += 8) {
        unsigned ah[4], al[4];
        split32(a0p[kk + t],     ah[0], al[0]);
        split32(a1p[kk + t],     ah[1], al[1]);
        split32(a0p[kk + t + 4], ah[2], al[2]);
        split32(a1p[kk + t + 4], ah[3], al[3]);
        unsigned bh0, bl0, bh1, bl1, ch0, cl0, ch1, cl1;
        split32(b0p[kk + t],     bh0, bl0);
        split32(b0p[kk + t + 4], bh1, bl1);
        split32(b1p[kk + t],     ch0, cl0);
        split32(b1p[kk + t + 4], ch1, cl1);
        mma3x(d0, ah, al, bh0, bh1, bl0, bl1);
        mma3x(d1, ah, al, ch0, ch1, cl0, cl1);
    }

    float* rw = red + warp * 256;
    rw[g * 16 + 2 * t]            = d0[0];
    rw[g * 16 + 2 * t + 1]        = d0[1];
    rw[(g + 8) * 16 + 2 * t]      = d0[2];
    rw[(g + 8) * 16 + 2 * t + 1]  = d0[3];
    rw[g * 16 + 8 + 2 * t]        = d1[0];
    rw[g * 16 + 8 + 2 * t + 1]    = d1[1];
    rw[(g + 8) * 16 + 8 + 2 * t]  = d1[2];
    rw[(g + 8) * 16 + 8 + 2 * t + 1] = d1[3];
    __syncthreads();

    for (int o = tid; o < 256; o += 128) {
        float v = red[o] + red[256 + o] + red[512 + o] + red[768 + o];
        int r = o >> 4, c = o & 15;
        int row = m0 + r, col = n0 + c;
        if (bias) v += bias[col];
        if (act) v = gelu_f(v);
        if (row < M) C[(long)row * N + col] = v;
    }
}

// grid (N/16, ceil(M/16), zsplit). Slice s covers K/zs; bias only on s==0;
// act only valid with zs==1 (caller discipline).
__global__ void __launch_bounds__(128) k_tgemm(
    const float* __restrict__ A, int lda, const float* __restrict__ W, int ldw,
    const float* __restrict__ bias, float* __restrict__ C,
    int M, int N, int K, int act, int bcmod)
{
    __shared__ float red[1024];
    int zs = gridDim.z, s = blockIdx.z;
    int klen = K / zs;
    tgemm_body(A, lda, W, ldw, (s == 0) ? bias : (const float*)0,
               C + (long)s * M * N, M, N, act, bcmod,
               blockIdx.y * 16, blockIdx.x * 16, s * klen, klen, red);
}

// ---------------- head precompute mega-kernel --------------------------------
// [0,640)      sW  = objf @ pe1_w[0:H]^T     (320 x 512)
// [640,1280)   oW  = objf @ pe1_w[H:2H]^T    (320 x 512)
// [1280,1920)  kv0 = tctx @ ca_in_w0[kv]^T   (160 x 1024)
// [1920,2560)  kv1 = tctx @ ca_in_w1[kv]^T   (160 x 1024)
// [2560,2592)  fused head weights g_wf/g_bf (32 rows, 27..31 zero)
__global__ void __launch_bounds__(128) k_headpre(
    const float* __restrict__ objf, const float* __restrict__ tctx,
    const float* __restrict__ pe1_w,
    const float* __restrict__ ca_in_w, const float* __restrict__ ca_in_b,
    const float* __restrict__ pred_w, const float* __restrict__ pred_b,
    const float* __restrict__ ex_w, const float* __restrict__ ex_b,
    const float* __restrict__ pe2_w, const float* __restrict__ pe2_b)
{
    __shared__ float red[1024];
    int blk = blockIdx.x;
    if (blk < 1280) {
        int which = blk >= 640;
        int idx = blk - which * 640;
        tgemm_body(objf, H, pe1_w + which * H, 3 * H, 0, which ? g_ow : g_sw,
                   BSZ * NOBJ, H, 0, 0, (idx >> 5) * 16, (idx & 31) * 16, 0, H, red);
        return;
    }
    blk -= 1280;
    if (blk < 1280) {
        int l = blk >= 640;
        int idx = blk - l * 640;
        tgemm_body(tctx, H, ca_in_w + (long)l * 3 * H * H + (long)H * H, H,
                   ca_in_b + l * 3 * H + H, g_kv + (long)l * BSZ * TC * 2 * H,
                   BSZ * TC, 2 * H, 0, 0, (idx >> 6) * 16, (idx & 63) * 16, 0, H, red);
        return;
    }
    int j = blk - 1280;   // 0..31
    int tid = threadIdx.x;
    int c0 = tid * 4;
    if (j >= 27) {
        *(float4*)&g_wf[j * H + c0] = make_float4(0.f, 0.f, 0.f, 0.f);
        if (tid == 0) g_bf[j] = 0.f;
        return;
    }
    const float* wc = (j < NPRED) ? (pred_w + j * H) : ex_w;
    float4 s = make_float4(0.f, 0.f, 0.f, 0.f);
    for (int o = 0; o < H; o++) {
        float w = wc[o];
        float4 p = *(const float4*)&pe2_w[(long)o * H + c0];
        s.x += w * p.x; s.y += w * p.y; s.z += w * p.z; s.w += w * p.w;
    }
    *(float4*)&g_wf[j * H + c0] = s;
    __shared__ float sm[4];
    float bsum = 0.f;
    for (int o = tid; o < H; o += 128) bsum += wc[o] * pe2_b[o];
    #pragma unroll
    for (int o = 16; o; o >>= 1) bsum += __shfl_xor_sync(0xffffffffu, bsum, o);
    if ((tid & 31) == 0) sm[tid >> 5] = bsum;
    __syncthreads();
    if (tid == 0) g_bf[j] = ((j < NPRED) ? pred_b[j] : ex_b[0]) + sm[0] + sm[1] + sm[2] + sm[3];
}

// ---------------- tiny multi-head attention (proven) -------------------------
__global__ void attn_kernel(const float* __restrict__ q, int qstride,
                            const float* __restrict__ k, const float* __restrict__ v, int kvstride,
                            float* __restrict__ out,
                            int Tq, int Tk, float scale)
{
    int h = blockIdx.x, b = blockIdx.y;
    __shared__ float qs[MAXF][DH], ks[TC][DH], vs[TC][DH], sc[MAXF][TC];
    int t = threadIdx.x;  // 64
    for (int i = 0; i < Tq; i++) qs[i][t] = q[(long)(b * Tq + i) * qstride + h * DH + t];
    for (int j = 0; j < Tk; j++) {
        ks[j][t] = k[(long)(b * Tk + j) * kvstride + h * DH + t];
        vs[j][t] = v[(long)(b * Tk + j) * kvstride + h * DH + t];
    }
    __syncthreads();
    if (t < Tq * Tk) {
        int ti = t / Tk, tj = t % Tk;
        float s = 0.f;
        #pragma unroll
        for (int d = 0; d < DH; d++) s += qs[ti][d] * ks[tj][d];
        sc[ti][tj] = s * scale;
    }
    __syncthreads();
    if (t < Tq) {
        float mx = -1e30f;
        for (int j = 0; j < Tk; j++) mx = fmaxf(mx, sc[t][j]);
        float sum = 0.f;
        for (int j = 0; j < Tk; j++) { float e = expf(sc[t][j] - mx); sc[t][j] = e; sum += e; }
        float inv = 1.f / sum;
        for (int j = 0; j < Tk; j++) sc[t][j] *= inv;
    }
    __syncthreads();
    for (int ti = 0; ti < Tq; ti++) {
        float o = 0.f;
        for (int j = 0; j < Tk; j++) o += sc[ti][j] * vs[j][t];
        out[(long)(b * Tq + ti) * H + h * DH + t] = o;
    }
}

// ---------------- layernorm: out = LN(sum_s x_s + res); optional 2nd LN -> ctx
__global__ void ln_kernel(const float* __restrict__ x, int ssz, int nsum,
                          const float* __restrict__ res, int resmod,
                          const float* __restrict__ w, const float* __restrict__ b,
                          float* __restrict__ out,
                          const float* __restrict__ fw, const float* __restrict__ fb,
                          float* __restrict__ ctxout)
{
    int row = blockIdx.x;
    int t = threadIdx.x;
    __shared__ float sm1[4], sm2[4];
    float v[4];
    long rrow = resmod ? (row % resmod) : row;
    float s1 = 0.f, s2 = 0.f;
    #pragma unroll
    for (int i = 0; i < 4; i++) {
        int c = t + i * 128;
        float val = res[rrow * H + c];
        for (int s = 0; s < nsum; s++) val += x[(long)s * ssz + (long)row * H + c];
        v[i] = val; s1 += val; s2 += val * val;
    }
    #pragma unroll
    for (int o = 16; o; o >>= 1) {
        s1 += __shfl_xor_sync(0xffffffffu, s1, o);
        s2 += __shfl_xor_sync(0xffffffffu, s2, o);
    }
    if ((t & 31) == 0) { sm1[t >> 5] = s1; sm2[t >> 5] = s2; }
    __syncthreads();
    float S1 = sm1[0] + sm1[1] + sm1[2] + sm1[3];
    float S2 = sm2[0] + sm2[1] + sm2[2] + sm2[3];
    float mean = S1 * (1.f / H);
    float var = S2 * (1.f / H) - mean * mean;
    float inv = rsqrtf(var + 1e-5f);
    float y[4];
    #pragma unroll
    for (int i = 0; i < 4; i++) {
        int c = t + i * 128;
        y[i] = (v[i] - mean) * inv * w[c] + b[c];
        out[(long)row * H + c] = y[i];
    }
    if (fw) {
        float t1 = 0.f, t2 = 0.f;
        #pragma unroll
        for (int i = 0; i < 4; i++) { t1 += y[i]; t2 += y[i] * y[i]; }
        #pragma unroll
        for (int o = 16; o; o >>= 1) {
            t1 += __shfl_xor_sync(0xffffffffu, t1, o);
            t2 += __shfl_xor_sync(0xffffffffu, t2, o);
        }
        __syncthreads();
        if ((t & 31) == 0) { sm1[t >> 5] = t1; sm2[t >> 5] = t2; }
        __syncthreads();
        float T1 = sm1[0] + sm1[1] + sm1[2] + sm1[3];
        float T2 = sm2[0] + sm2[1] + sm2[2] + sm2[3];
        float m2 = T1 * (1.f / H);
        float v2 = T2 * (1.f / H) - m2 * m2;
        float i2 = rsqrtf(v2 + 1e-5f);
        #pragma unroll
        for (int i = 0; i < 4; i++) {
            int c = t + i * 128;
            ctxout[(long)row * H + c] = (y[i] - m2) * i2 * fw[c] + fb[c];
        }
    }
}

// ---------------- fused pair head: stage 16 gelu'd rows, mma vs g_wf ---------
// grid = Rtot/16; 128 thr. 4 warps split K=512; 16m x 32n tile via 4 mma frags.
__global__ void __launch_bounds__(128) k_pairh(float* __restrict__ out, int Fh, int Rtot)
{
    __shared__ float hs[16 * 516];
    __shared__ float red[4 * 16 * 32];
    int tid = threadIdx.x, warp = tid >> 5, lane = tid & 31;
    int g = lane >> 2, t = lane & 3;
    int row0 = blockIdx.x * 16;

    // stage h = gelu(sW + oW + cW)
    for (int e = tid; e < 16 * H; e += 128) {
        int r = e >> 9, c = e & (H - 1);
        int row = row0 + r;
        int p = row % NP;
        int bfi = row / NP;
        int f = bfi % Fh;
        int b = bfi / Fh;
        int i = p / (NOBJ - 1);
        int jr = p % (NOBJ - 1);
        int jo = jr + (jr >= i ? 1 : 0);
        float hv = g_sw[(long)(b * NOBJ + i) * H + c] + g_ow[(long)(b * NOBJ + jo) * H + c]
                 + g_cw[(long)(b * Fh + f) * H + c];
        hs[r * 516 + c] = gelu_f(hv);
    }
    __syncthreads();

    // mma: this warp covers K [warp*128, warp*128+128)
    float d[4][4];
    #pragma unroll
    for (int f = 0; f < 4; f++)
        #pragma unroll
        for (int q = 0; q < 4; q++) d[f][q] = 0.f;
    int kb = warp * 128;
    #pragma unroll 2
    for (int kk = kb; kk < kb + 128; kk += 8) {
        unsigned ah[4], al[4];
        split32(hs[g * 516 + kk + t],           ah[0], al[0]);
        split32(hs[(g + 8) * 516 + kk + t],     ah[1], al[1]);
        split32(hs[g * 516 + kk + t + 4],       ah[2], al[2]);
        split32(hs[(g + 8) * 516 + kk + t + 4], ah[3], al[3]);
        #pragma unroll
        for (int f = 0; f < 4; f++) {
            unsigned bh0, bl0, bh1, bl1;
            split32(g_wf[(long)(f * 8 + g) * H + kk + t],     bh0, bl0);
            split32(g_wf[(long)(f * 8 + g) * H + kk + t + 4], bh1, bl1);
            mma3x(d[f], ah, al, bh0, bh1, bl0, bl1);
        }
    }
    float* rw = red + warp * 512;
    #pragma unroll
    for (int f = 0; f < 4; f++) {
        int cb = f * 8;
        rw[g * 32 + cb + 2 * t]           = d[f][0];
        rw[g * 32 + cb + 2 * t + 1]       = d[f][1];
        rw[(g + 8) * 32 + cb + 2 * t]     = d[f][2];
        rw[(g + 8) * 32 + cb + 2 * t + 1] = d[f][3];
    }
    __syncthreads();
    for (int o = tid; o < 512; o += 128) {
        float v = red[o] + red[512 + o] + red[1024 + o] + red[1536 + o];
        int r = o >> 5, c = o & 31;
        v += g_bf[c];
        int row = row0 + r;
        if (c < NPRED)       out[(long)row * NPRED + c] = v;
        else if (c == NPRED) out[(long)Rtot * NPRED + row] = v;
    }
}

// ---------------- host orchestration ----------------
extern "C" void kernel_launch(void* const* d_in, const int* in_sizes, int n_in,
                              void* d_out, int out_size)
{
    const float* tctx    = (const float*)d_in[0];
    const float* objf    = (const float*)d_in[1];
    const float* fq      = (const float*)d_in[2];
    const float* sa_in_w = (const float*)d_in[3];
    const float* sa_in_b = (const float*)d_in[4];
    const float* sa_out_w= (const float*)d_in[5];
    const float* sa_out_b= (const float*)d_in[6];
    const float* ca_in_w = (const float*)d_in[7];
    const float* ca_in_b = (const float*)d_in[8];
    const float* ca_out_w= (const float*)d_in[9];
    const float* ca_out_b= (const float*)d_in[10];
    const float* ff1_w   = (const float*)d_in[11];
    const float* ff1_b   = (const float*)d_in[12];
    const float* ff2_w   = (const float*)d_in[13];
    const float* ff2_b   = (const float*)d_in[14];
    const float* n1_w    = (const float*)d_in[15];
    const float* n1_b    = (const float*)d_in[16];
    const float* n2_w    = (const float*)d_in[17];
    const float* n2_b    = (const float*)d_in[18];
    const float* n3_w    = (const float*)d_in[19];
    const float* n3_b    = (const float*)d_in[20];
    const float* norm_w  = (const float*)d_in[21];
    const float* norm_b  = (const float*)d_in[22];
    const float* pe1_w   = (const float*)d_in[23];
    const float* pe1_b   = (const float*)d_in[24];
    const float* pe2_w   = (const float*)d_in[25];
    const float* pe2_b   = (const float*)d_in[26];
    const float* pred_w  = (const float*)d_in[27];
    const float* pred_b  = (const float*)d_in[28];
    const float* ex_w    = (const float*)d_in[29];
    const float* ex_b    = (const float*)d_in[30];
    (void)in_sizes; (void)n_in;

    int Fh = out_size / (BSZ * NP * (NPRED + 1));
    if (Fh < 1) Fh = 1;
    if (Fh > MAXF) Fh = MAXF;
    int Mq = BSZ * Fh;
    int MT = (Mq + 15) / 16;

    float *px, *pqkv, *pkv, *patt, *pproj, *pffh, *pctx, *pcw;
    cudaGetSymbolAddress((void**)&px,    g_px);
    cudaGetSymbolAddress((void**)&pqkv,  g_qkv);
    cudaGetSymbolAddress((void**)&pkv,   g_kv);
    cudaGetSymbolAddress((void**)&patt,  g_att);
    cudaGetSymbolAddress((void**)&pproj, g_proj);
    cudaGetSymbolAddress((void**)&pffh,  g_ffh);
    cudaGetSymbolAddress((void**)&pctx,  g_ctx);
    cudaGetSymbolAddress((void**)&pcw,   g_cw);

    // 1) all decoder-independent precompute in one launch (2592 blocks)
    k_headpre<<<2592, 128>>>(objf, tctx, pe1_w, ca_in_w, ca_in_b,
                             pred_w, pred_b, ex_w, ex_b, pe2_w, pe2_b);

    const float scale = 0.125f;
    for (int l = 0; l < NLAY; l++) {
        // SA qkv: M x 3H, K=H  (layer0 reads broadcast fq)
        k_tgemm<<<dim3(3 * H / 16, MT, 1), 128>>>(
            (l == 0) ? fq : px, H, sa_in_w + (long)l * 3 * H * H, H,
            sa_in_b + l * 3 * H, pqkv, Mq, 3 * H, H, 0, (l == 0) ? Fh : 0);
        attn_kernel<<<dim3(NH, BSZ), 64>>>(pqkv, 3 * H, pqkv + H, pqkv + 2 * H, 3 * H,
                                           patt, Fh, Fh, scale);
        // SA out-proj: z-split 4, LN sums slices
        k_tgemm<<<dim3(H / 16, MT, 4), 128>>>(
            patt, H, sa_out_w + (long)l * H * H, H, sa_out_b + l * H,
            pproj, Mq, H, H, 0, 0);
        ln_kernel<<<Mq, 128>>>(pproj, Mq * H, 4, (l == 0) ? fq : px, (l == 0) ? Fh : 0,
                               n1_w + l * H, n1_b + l * H, px, nullptr, nullptr, nullptr);
        // CA q-proj (kv precomputed)
        k_tgemm<<<dim3(H / 16, MT, 1), 128>>>(
            px, H, ca_in_w + (long)l * 3 * H * H, H, ca_in_b + l * 3 * H,
            pqkv, Mq, H, H, 0, 0);
        const float* kvl = pkv + (long)l * BSZ * TC * 2 * H;
        attn_kernel<<<dim3(NH, BSZ), 64>>>(pqkv, H, kvl, kvl + H, 2 * H,
                                           patt, Fh, TC, scale);
        k_tgemm<<<dim3(H / 16, MT, 4), 128>>>(
            patt, H, ca_out_w + (long)l * H * H, H, ca_out_b + l * H,
            pproj, Mq, H, H, 0, 0);
        ln_kernel<<<Mq, 128>>>(pproj, Mq * H, 4, px, 0,
                               n2_w + l * H, n2_b + l * H, px, nullptr, nullptr, nullptr);
        // FFN
        k_tgemm<<<dim3(FFD / 16, MT, 1), 128>>>(
            px, H, ff1_w + (long)l * FFD * H, H, ff1_b + l * FFD,
            pffh, Mq, FFD, H, 1, 0);
        k_tgemm<<<dim3(H / 16, MT, 4), 128>>>(
            pffh, FFD, ff2_w + (long)l * H * FFD, FFD, ff2_b + l * H,
            pproj, Mq, H, FFD, 0, 0);
        int last = (l == NLAY - 1);
        ln_kernel<<<Mq, 128>>>(pproj, Mq * H, 4, px, 0,
                               n3_w + l * H, n3_b + l * H, px,
                               last ? norm_w : nullptr, last ? norm_b : nullptr, pctx);
    }

    // ctx projection through pe1 ctx slice
    k_tgemm<<<dim3(H / 16, MT, 1), 128>>>(
        pctx, H, pe1_w + 2 * H, 3 * H, pe1_b, pcw, Mq, H, H, 0, 0);

    // fused pair head (tensor-core)
    int Rtot = BSZ * Fh * NP;
    k_pairh<<<Rtot / 16, 128>>>((float*)d_out, Fh, Rtot);
}